// round 4
// baseline (speedup 1.0000x reference)
#include <cuda_runtime.h>

#define B_ 64
#define S_ 2048
#define I_ 128
#define H_ 512
#define O_ 128

// ---------------- scratch (device globals: no allocations allowed) ----------
__device__ float g_xin[(size_t)B_ * S_ * H_];   // input projection (B,S,H)
__device__ float g_hs [(size_t)B_ * S_ * H_];   // hidden states   (B,S,H)

// ---------------- helpers ----------------------------------------------------
__device__ __forceinline__ unsigned long long ffma2(unsigned long long a,
                                                    unsigned long long b,
                                                    unsigned long long c) {
    unsigned long long d;
    asm("fma.rn.f32x2 %0, %1, %2, %3;" : "=l"(d) : "l"(a), "l"(b), "l"(c));
    return d;
}
__device__ __forceinline__ unsigned long long pack2(float x, float y) {
    unsigned long long p;
    asm("mov.b64 %0, {%1, %2};" : "=l"(p) : "f"(x), "f"(y));
    return p;
}
__device__ __forceinline__ float2 unpack2(unsigned long long p) {
    float2 r;
    asm("mov.b64 {%0, %1}, %2;" : "=f"(r.x), "=f"(r.y) : "l"(p));
    return r;
}
__device__ __forceinline__ unsigned smem_u32(const void* p) {
    unsigned a;
    asm("{ .reg .u64 t; cvta.to.shared.u64 t, %1; cvt.u32.u64 %0, t; }"
        : "=r"(a) : "l"(p));
    return a;
}
__device__ __forceinline__ unsigned ctarank() {
    unsigned r; asm("mov.u32 %0, %%cluster_ctarank;" : "=r"(r)); return r;
}
__device__ __forceinline__ unsigned mapa_u32(unsigned addr, unsigned rank) {
    unsigned r;
    asm("mapa.shared::cluster.u32 %0, %1, %2;" : "=r"(r) : "r"(addr), "r"(rank));
    return r;
}
__device__ __forceinline__ void mbar_init(unsigned a, unsigned cnt) {
    asm volatile("mbarrier.init.shared.b64 [%0], %1;" :: "r"(a), "r"(cnt) : "memory");
}
__device__ __forceinline__ void mbar_arrive_remote(unsigned a_remote) {
    asm volatile("mbarrier.arrive.release.cluster.shared::cluster.b64 _, [%0];"
                 :: "r"(a_remote) : "memory");
}
__device__ __forceinline__ void st_cluster_f32(unsigned a_remote, float v) {
    asm volatile("st.shared::cluster.f32 [%0], %1;" :: "r"(a_remote), "f"(v) : "memory");
}
__device__ __forceinline__ void mbar_wait_cluster(unsigned a, unsigned parity) {
    unsigned done;
    asm volatile(
        "{\n\t.reg .pred p;\n\t"
        "mbarrier.try_wait.parity.acquire.cluster.shared::cta.b64 p, [%1], %2;\n\t"
        "selp.b32 %0, 1, 0, p;\n\t}"
        : "=r"(done) : "r"(a), "r"(parity) : "memory");
    if (!done) {
        asm volatile(
            "{\n\t.reg .pred P1;\n\t"
            "WL_%=:\n\t"
            "mbarrier.try_wait.parity.acquire.cluster.shared::cta.b64 P1, [%0], %1, 0x989680;\n\t"
            "@P1 bra.uni WD_%=;\n\t"
            "bra.uni WL_%=;\n\t"
            "WD_%=:\n\t}"
            :: "r"(a), "r"(parity) : "memory");
    }
}

// permuted h layout: k = kg*64 + i*4 + r  ->  phys = i*32 + kg*4 + r
// (lane kg reads 16B chunks that are consecutive across the 8 kg lanes)
__device__ __forceinline__ int hphys(int k) {
    return (((k >> 2) & 15) << 5) | ((k >> 6) << 2) | (k & 3);
}

// ---------------- tiled fp32 GEMM:  C[M,N] = A[M,K] @ B[N,K]^T + bias --------
template <int N, int K, bool SRC_HS, bool DST_XIN>
__global__ __launch_bounds__(256) void gemm_kernel(const float* __restrict__ Ap,
                                                   const float* __restrict__ Bm,
                                                   const float* __restrict__ bias,
                                                   float* __restrict__ Cp) {
    __shared__ __align__(16) float Ast[32][132];
    __shared__ __align__(16) float Bst[32][132];
    const float* A = SRC_HS ? g_hs : Ap;
    float* C = DST_XIN ? g_xin : Cp;

    const int tid = threadIdx.x;
    const int bm = blockIdx.x, bn = blockIdx.y;
    const float* Ab = A + (size_t)bm * 128 * K;
    const float* Bb = Bm + (size_t)bn * 128 * K;

    const int tx = tid & 15, ty = tid >> 4;
    unsigned long long acc2[4][8];
#pragma unroll
    for (int i = 0; i < 4; i++)
#pragma unroll
        for (int j = 0; j < 8; j++) acc2[i][j] = 0ull;

    for (int k0 = 0; k0 < K; k0 += 32) {
#pragma unroll
        for (int u = 0; u < 4; u++) {
            int idx4 = tid + u * 256;
            int m = idx4 >> 3;
            int kq = (idx4 & 7) * 4;
            float4 va = *(const float4*)&Ab[(size_t)m * K + k0 + kq];
            Ast[kq + 0][m] = va.x; Ast[kq + 1][m] = va.y;
            Ast[kq + 2][m] = va.z; Ast[kq + 3][m] = va.w;
            float4 vb = *(const float4*)&Bb[(size_t)m * K + k0 + kq];
            Bst[kq + 0][m] = vb.x; Bst[kq + 1][m] = vb.y;
            Bst[kq + 2][m] = vb.z; Bst[kq + 3][m] = vb.w;
        }
        __syncthreads();
#pragma unroll
        for (int kc = 0; kc < 32; kc++) {
            float4 a0 = *(const float4*)&Ast[kc][ty * 8];
            float4 a1 = *(const float4*)&Ast[kc][ty * 8 + 4];
            float4 b0 = *(const float4*)&Bst[kc][tx * 8];
            float4 b1 = *(const float4*)&Bst[kc][tx * 8 + 4];
            unsigned long long A2[4] = {pack2(a0.x, a0.y), pack2(a0.z, a0.w),
                                        pack2(a1.x, a1.y), pack2(a1.z, a1.w)};
            float bb[8] = {b0.x, b0.y, b0.z, b0.w, b1.x, b1.y, b1.z, b1.w};
#pragma unroll
            for (int j = 0; j < 8; j++) {
                unsigned long long B2 = pack2(bb[j], bb[j]);
#pragma unroll
                for (int i = 0; i < 4; i++) acc2[i][j] = ffma2(A2[i], B2, acc2[i][j]);
            }
        }
        __syncthreads();
    }
#pragma unroll
    for (int i = 0; i < 4; i++) {
        size_t m0 = (size_t)bm * 128 + ty * 8 + 2 * i;
#pragma unroll
        for (int j = 0; j < 8; j++) {
            int n = bn * 128 + tx * 8 + j;
            float2 v = unpack2(acc2[i][j]);
            C[m0 * N + n]       = v.x + bias[n];
            C[(m0 + 1) * N + n] = v.y + bias[n];
        }
    }
}

// ---------------- recurrent scan: 8-CTA cluster, shfl reduce, remote STS -----
// cluster = 8 CTAs = 8 output-slices (64 cols) of one batch-group (4 batches).
// warp w: outputs j = rank*64 + w*4 + (lane>>3), k-slice kg = lane&7 (64-wide).
// Reduction across kg via shfl.bfly (intra-warp). Producers (kg==0 lanes)
// write h to local + 7 peers via st.shared::cluster; elected thread fences and
// arrives on peers' count-7 mbarrier. Double-buffered h, permuted layout.
__global__ __launch_bounds__(512, 1) __cluster_dims__(8, 1, 1)
void scan_kernel(const float* __restrict__ h0,
                 const float* __restrict__ Wrec,
                 float* __restrict__ hfinal) {
    __shared__ __align__(16) float h_s[2][4][H_];     // 16 KB, permuted k layout
    __shared__ __align__(8) unsigned long long mbar[2];

    const int tid = threadIdx.x;
    const int bg = blockIdx.x >> 3;                 // batch-group 0..15
    const unsigned rank = ctarank();                // 0..7 = output slice
    const int w = tid >> 5, lane = tid & 31;
    const int kg = lane & 7;                        // k-slice 0..7
    const int jo = lane >> 3;                       // output-within-warp 0..3
    const int jg = (int)rank * 64 + w * 4 + jo;     // global output col
    const int k0 = kg * 64;

    const unsigned mb = smem_u32(&mbar[0]);
    const unsigned hbase = smem_u32(&h_s[0][0][0]);

    // ---- W_rec[jg][k0..k0+63] -> 32 f32x2 register pairs
    unsigned long long Wr[32];
    {
        const float4* wp = (const float4*)&Wrec[(size_t)jg * H_ + k0];
#pragma unroll
        for (int i = 0; i < 16; i++) {
            float4 v = wp[i];
            Wr[2 * i]     = pack2(v.x, v.y);
            Wr[2 * i + 1] = pack2(v.z, v.w);
        }
    }

    // ---- peer smem bases (7 peers)
    unsigned peer_h[7], peer_mb[7];
#pragma unroll
    for (int r = 0; r < 7; r++) {
        unsigned pr = (rank + 1 + r) & 7;
        peer_h[r] = mapa_u32(hbase, pr);
        peer_mb[r] = mapa_u32(mb, pr);
    }

    // ---- mbar init (count 7 = one arrive per peer CTA)
    if (tid == 0) { mbar_init(mb, 7); mbar_init(mb + 8, 7); }

    // ---- h0 -> h_s[0] permuted: tid -> (b, 4 consecutive k)
    {
        int b = tid >> 7, q = tid & 127;
        float4 v = *(const float4*)&h0[(size_t)(bg * 4 + b) * H_ + q * 4];
        *(float4*)&h_s[0][b][hphys(q * 4)] = v;
    }
    __syncthreads();
    asm volatile("barrier.cluster.arrive.aligned;" ::: "memory");
    asm volatile("barrier.cluster.wait.aligned;" ::: "memory");

    // ---- producer lanes (kg==0) prefetch xin for t=0
    float xr[4];
    if (kg == 0) {
#pragma unroll
        for (int b = 0; b < 4; b++)
            xr[b] = g_xin[((size_t)(bg * 4 + b) * S_) * H_ + jg];
    }

    unsigned p0 = 0, p1 = 0;

    for (int t = 0; t < S_; t++) {
        const int cur = t & 1;
        if (t > 0) {
            if (cur == 0) { mbar_wait_cluster(mb, p0); if (tid == 0) {} p0 ^= 1; }
            else          { mbar_wait_cluster(mb + 8, p1); p1 ^= 1; }
        }

        // ---- partial GEMM over 64-wide K slice, 4 batches (f32x2)
        unsigned long long a0 = 0, a1 = 0, a2 = 0, a3 = 0;
        {
            // lane kg reads 16B chunks at phys = i*128B + kg*16B (coalesced)
            const unsigned base = hbase + (unsigned)(cur * 8192) + (unsigned)(kg * 16);
#pragma unroll
            for (int i = 0; i < 16; i++) {
                unsigned off = (unsigned)(i * 128);
                ulonglong2 u0 = *(const ulonglong2*)(unsigned long long)0;  // placeholder
                // use inline asm LDS via pointers instead:
                (void)u0; (void)off;
            }
        }
        // (real loads below — structured loop)
        {
            const char* hb0 = (const char*)&h_s[cur][0][0] + kg * 16;
            const char* hb1 = (const char*)&h_s[cur][1][0] + kg * 16;
            const char* hb2 = (const char*)&h_s[cur][2][0] + kg * 16;
            const char* hb3 = (const char*)&h_s[cur][3][0] + kg * 16;
#pragma unroll
            for (int i = 0; i < 16; i++) {
                ulonglong2 u0 = *(const ulonglong2*)(hb0 + i * 128);
                a0 = ffma2(Wr[2 * i], u0.x, a0);
                a0 = ffma2(Wr[2 * i + 1], u0.y, a0);
                ulonglong2 u1 = *(const ulonglong2*)(hb1 + i * 128);
                a1 = ffma2(Wr[2 * i], u1.x, a1);
                a1 = ffma2(Wr[2 * i + 1], u1.y, a1);
                ulonglong2 u2 = *(const ulonglong2*)(hb2 + i * 128);
                a2 = ffma2(Wr[2 * i], u2.x, a2);
                a2 = ffma2(Wr[2 * i + 1], u2.y, a2);
                ulonglong2 u3 = *(const ulonglong2*)(hb3 + i * 128);
                a3 = ffma2(Wr[2 * i], u3.x, a3);
                a3 = ffma2(Wr[2 * i + 1], u3.y, a3);
            }
        }
        float2 f0 = unpack2(a0), f1 = unpack2(a1), f2 = unpack2(a2), f3 = unpack2(a3);
        float s0 = f0.x + f0.y, s1 = f1.x + f1.y, s2 = f2.x + f2.y, s3 = f3.x + f3.y;

        // ---- intra-warp reduce across the 8 kg lanes (xor 1,2,4)
#pragma unroll
        for (int m = 1; m < 8; m <<= 1) {
            s0 += __shfl_xor_sync(0xFFFFFFFF, s0, m);
            s1 += __shfl_xor_sync(0xFFFFFFFF, s1, m);
            s2 += __shfl_xor_sync(0xFFFFFFFF, s2, m);
            s3 += __shfl_xor_sync(0xFFFFFFFF, s3, m);
        }

        const int nxt = cur ^ 1;
        if (kg == 0) {
            float sums[4] = {s0, s1, s2, s3};
            const int pj = hphys(jg);
#pragma unroll
            for (int b = 0; b < 4; b++) {
                float hn = tanhf(sums[b] + xr[b]);
                int bglob = bg * 4 + b;
                g_hs[((size_t)bglob * S_ + t) * H_ + jg] = hn;
                if (t + 1 < S_) {
                    h_s[nxt][b][pj] = hn;
                    unsigned off = (unsigned)(nxt * 8192 + b * 2048 + pj * 4);
#pragma unroll
                    for (int r = 0; r < 7; r++) st_cluster_f32(peer_h[r] + off, hn);
                    xr[b] = g_xin[((size_t)bglob * S_ + (t + 1)) * H_ + jg];
                } else {
                    hfinal[(size_t)bglob * H_ + jg] = hn;
                }
            }
        }
        __syncthreads();

        // ---- publish: fence + arrive on all 7 peers' next-buffer mbar
        if (t + 1 < S_ && tid == 0) {
            asm volatile("fence.acq_rel.cluster;" ::: "memory");
#pragma unroll
            for (int r = 0; r < 7; r++) mbar_arrive_remote(peer_mb[r] + (unsigned)(nxt * 8));
        }
    }
}

// ---------------- launch ------------------------------------------------------
extern "C" void kernel_launch(void* const* d_in, const int* in_sizes, int n_in,
                              void* d_out, int out_size) {
    const float* inputs  = (const float*)d_in[0];
    const float* h0      = (const float*)d_in[1];
    const float* W_in_w  = (const float*)d_in[2];
    const float* W_in_b  = (const float*)d_in[3];
    const float* W_rec_w = (const float*)d_in[4];
    const float* W_out_w = (const float*)d_in[5];
    const float* W_out_b = (const float*)d_in[6];

    float* out    = (float*)d_out;                      // (B,S,O)
    float* hfinal = out + (size_t)B_ * S_ * O_;         // (B,H)

    // 1) xin = inputs @ W_in^T + b   -> g_xin
    {
        dim3 grid(B_ * S_ / 128, H_ / 128);
        gemm_kernel<H_, I_, false, true><<<grid, 256>>>(inputs, W_in_w, W_in_b, nullptr);
    }
    // 2) sequential scan: 16 clusters x 8 CTAs
    scan_kernel<<<128, 512>>>(h0, W_rec_w, hfinal);

    // 3) outputs = hs @ W_out^T + b  -> d_out
    {
        dim3 grid(B_ * S_ / 128, O_ / 128);
        gemm_kernel<O_, H_, true, false><<<grid, 256>>>(nullptr, W_out_w, W_out_b, out);
    }
}

// round 5
// speedup vs baseline: 1.3818x; 1.3818x over previous
#include <cuda_runtime.h>

#define B_ 64
#define S_ 2048
#define I_ 128
#define H_ 512
#define O_ 128

// ---------------- scratch (device globals: no allocations allowed) ----------
__device__ float g_xin[(size_t)B_ * S_ * H_];   // input projection (B,S,H)
__device__ float g_hs [(size_t)B_ * S_ * H_];   // hidden states   (B,S,H)

// ---------------- helpers ----------------------------------------------------
__device__ __forceinline__ unsigned long long ffma2(unsigned long long a,
                                                    unsigned long long b,
                                                    unsigned long long c) {
    unsigned long long d;
    asm("fma.rn.f32x2 %0, %1, %2, %3;" : "=l"(d) : "l"(a), "l"(b), "l"(c));
    return d;
}
__device__ __forceinline__ unsigned long long pack2(float x, float y) {
    unsigned long long p;
    asm("mov.b64 %0, {%1, %2};" : "=l"(p) : "f"(x), "f"(y));
    return p;
}
__device__ __forceinline__ float2 unpack2(unsigned long long p) {
    float2 r;
    asm("mov.b64 {%0, %1}, %2;" : "=f"(r.x), "=f"(r.y) : "l"(p));
    return r;
}
__device__ __forceinline__ unsigned smem_u32(const void* p) {
    unsigned a;
    asm("{ .reg .u64 t; cvta.to.shared.u64 t, %1; cvt.u32.u64 %0, t; }"
        : "=r"(a) : "l"(p));
    return a;
}
__device__ __forceinline__ unsigned ctarank() {
    unsigned r; asm("mov.u32 %0, %%cluster_ctarank;" : "=r"(r)); return r;
}
__device__ __forceinline__ unsigned mapa_u32(unsigned addr, unsigned rank) {
    unsigned r;
    asm("mapa.shared::cluster.u32 %0, %1, %2;" : "=r"(r) : "r"(addr), "r"(rank));
    return r;
}
__device__ __forceinline__ void mbar_init(unsigned a, unsigned cnt) {
    asm volatile("mbarrier.init.shared.b64 [%0], %1;" :: "r"(a), "r"(cnt) : "memory");
}
__device__ __forceinline__ void mbar_arrive_cluster(unsigned a_remote) {
    asm volatile("mbarrier.arrive.release.cluster.shared::cluster.b64 _, [%0];"
                 :: "r"(a_remote) : "memory");
}
__device__ __forceinline__ void st_cluster_f32(unsigned a_remote, float v) {
    asm volatile("st.shared::cluster.f32 [%0], %1;" :: "r"(a_remote), "f"(v) : "memory");
}
__device__ __forceinline__ void mbar_wait_cluster(unsigned a, unsigned parity) {
    unsigned done;
    asm volatile(
        "{\n\t.reg .pred p;\n\t"
        "mbarrier.try_wait.parity.acquire.cluster.shared::cta.b64 p, [%1], %2;\n\t"
        "selp.b32 %0, 1, 0, p;\n\t}"
        : "=r"(done) : "r"(a), "r"(parity) : "memory");
    if (!done) {
        asm volatile(
            "{\n\t.reg .pred P1;\n\t"
            "WL_%=:\n\t"
            "mbarrier.try_wait.parity.acquire.cluster.shared::cta.b64 P1, [%0], %1, 0x989680;\n\t"
            "@P1 bra.uni WD_%=;\n\t"
            "bra.uni WL_%=;\n\t"
            "WD_%=:\n\t}"
            :: "r"(a), "r"(parity) : "memory");
    }
}

// ---------------- tiled fp32 GEMM:  C[M,N] = A[M,K] @ B[N,K]^T + bias --------
template <int N, int K, bool SRC_HS, bool DST_XIN>
__global__ __launch_bounds__(256) void gemm_kernel(const float* __restrict__ Ap,
                                                   const float* __restrict__ Bm,
                                                   const float* __restrict__ bias,
                                                   float* __restrict__ Cp) {
    __shared__ __align__(16) float Ast[32][132];
    __shared__ __align__(16) float Bst[32][132];
    const float* A = SRC_HS ? g_hs : Ap;
    float* C = DST_XIN ? g_xin : Cp;

    const int tid = threadIdx.x;
    const int bm = blockIdx.x, bn = blockIdx.y;
    const float* Ab = A + (size_t)bm * 128 * K;
    const float* Bb = Bm + (size_t)bn * 128 * K;

    const int tx = tid & 15, ty = tid >> 4;
    unsigned long long acc2[4][8];
#pragma unroll
    for (int i = 0; i < 4; i++)
#pragma unroll
        for (int j = 0; j < 8; j++) acc2[i][j] = 0ull;

    for (int k0 = 0; k0 < K; k0 += 32) {
#pragma unroll
        for (int u = 0; u < 4; u++) {
            int idx4 = tid + u * 256;
            int m = idx4 >> 3;
            int kq = (idx4 & 7) * 4;
            float4 va = *(const float4*)&Ab[(size_t)m * K + k0 + kq];
            Ast[kq + 0][m] = va.x; Ast[kq + 1][m] = va.y;
            Ast[kq + 2][m] = va.z; Ast[kq + 3][m] = va.w;
            float4 vb = *(const float4*)&Bb[(size_t)m * K + k0 + kq];
            Bst[kq + 0][m] = vb.x; Bst[kq + 1][m] = vb.y;
            Bst[kq + 2][m] = vb.z; Bst[kq + 3][m] = vb.w;
        }
        __syncthreads();
#pragma unroll
        for (int kc = 0; kc < 32; kc++) {
            float4 a0 = *(const float4*)&Ast[kc][ty * 8];
            float4 a1 = *(const float4*)&Ast[kc][ty * 8 + 4];
            float4 b0 = *(const float4*)&Bst[kc][tx * 8];
            float4 b1 = *(const float4*)&Bst[kc][tx * 8 + 4];
            unsigned long long A2[4] = {pack2(a0.x, a0.y), pack2(a0.z, a0.w),
                                        pack2(a1.x, a1.y), pack2(a1.z, a1.w)};
            float bb[8] = {b0.x, b0.y, b0.z, b0.w, b1.x, b1.y, b1.z, b1.w};
#pragma unroll
            for (int j = 0; j < 8; j++) {
                unsigned long long B2 = pack2(bb[j], bb[j]);
#pragma unroll
                for (int i = 0; i < 4; i++) acc2[i][j] = ffma2(A2[i], B2, acc2[i][j]);
            }
        }
        __syncthreads();
    }
#pragma unroll
    for (int i = 0; i < 4; i++) {
        size_t m0 = (size_t)bm * 128 + ty * 8 + 2 * i;
#pragma unroll
        for (int j = 0; j < 8; j++) {
            int n = bn * 128 + tx * 8 + j;
            float2 v = unpack2(acc2[i][j]);
            C[m0 * N + n]       = v.x + bias[n];
            C[(m0 + 1) * N + n] = v.y + bias[n];
        }
    }
}

// ---------------- recurrent scan --------------------------------------------
// cluster = 8 CTAs = 8 output-slices (64 cols) of one batch-group (4 batches).
// Lane (jo=lane>>3, kg=lane&7): output j = rank*64 + w*4 + jo, K-slice kg*64.
// h layout per buffer: [b][chunk]*16B, chunk(k) = ((k%64)/4)*8 + k/64, so the
// 8 kg lanes of a warp read 8 consecutive 16B chunks (128B, broadcast over jo).
// Reduce over kg via shfl.bfly; ALL lanes tanh; push = 4 st.shared::cluster.f32
// per warp (32 lanes, 8 CTAs each). One __syncthreads + elected fence+arrive.
__global__ __launch_bounds__(512, 1) __cluster_dims__(8, 1, 1)
void scan_kernel(const float* __restrict__ h0,
                 const float* __restrict__ Wrec,
                 float* __restrict__ hfinal) {
    __shared__ __align__(16) float h_s[2][4][H_];     // 16 KB
    __shared__ __align__(8) unsigned long long mbar[2];

    const int tid = threadIdx.x;
    const int bg = blockIdx.x >> 3;                 // batch-group 0..15
    const unsigned rank = ctarank();                // 0..7 = output slice
    const int w = tid >> 5, lane = tid & 31;
    const int kg = lane & 7;                        // K-slice 0..7 (64-wide)
    const int jo = lane >> 3;                       // 0..3
    const int jg = (int)rank * 64 + w * 4 + jo;     // global output col

    const unsigned mb = smem_u32(&mbar[0]);
    const unsigned hbase = smem_u32(&h_s[0][0][0]);

    // ---- W_rec[jg][kg*64 .. +63] as 32 k-pair-packed f32x2 regs
    unsigned long long Wr[32];
    {
        const float4* wp = (const float4*)&Wrec[(size_t)jg * H_ + kg * 64];
#pragma unroll
        for (int q = 0; q < 16; q++) {
            float4 v = wp[q];
            Wr[2 * q]     = pack2(v.x, v.y);
            Wr[2 * q + 1] = pack2(v.z, v.w);
        }
    }

    // ---- per-lane push base: peer rank 'kg', chunk (w*8+rank), word jo
    const unsigned push_base =
        mapa_u32(hbase, (unsigned)kg) + (unsigned)((w * 8 + (int)rank) * 16 + jo * 4);
    // ---- all 8 ranks' mbar bases for elected arrives
    unsigned peer_mb[8];
#pragma unroll
    for (int r = 0; r < 8; r++) peer_mb[r] = mapa_u32(mb, (unsigned)r);

    if (tid == 0) { mbar_init(mb, 8); mbar_init(mb + 8, 8); }

    // ---- h0 -> h_s[0]: tid -> (b = tid>>7, quad kq = tid&127)
    {
        int b = tid >> 7, kq = tid & 127;
        int chunk = (kq & 15) * 8 + (kq >> 4);
        float4 v = *(const float4*)&h0[(size_t)(bg * 4 + b) * H_ + kq * 4];
        *(float4*)((char*)h_s + b * 2048 + chunk * 16) = v;
    }
    __syncthreads();
    asm volatile("barrier.cluster.arrive.aligned;" ::: "memory");
    asm volatile("barrier.cluster.wait.aligned;" ::: "memory");

    // ---- xin for t=0 (per-lane: its j, 4 batches)
    float xr[4];
#pragma unroll
    for (int b = 0; b < 4; b++)
        xr[b] = g_xin[((size_t)(bg * 4 + b) * S_) * H_ + jg];

    unsigned p0 = 0, p1 = 0;

    for (int t = 0; t < S_; t++) {
        const int cur = t & 1, nxt = cur ^ 1;

        // ---- prefetch xin for t+1 (hidden under compute)
        float xn[4];
        if (t + 1 < S_) {
#pragma unroll
            for (int b = 0; b < 4; b++)
                xn[b] = g_xin[((size_t)(bg * 4 + b) * S_ + (t + 1)) * H_ + jg];
        }

        // ---- partial GEMM: 16 quads x 4 batches, k-pair packed f32x2
        unsigned long long acc[4] = {0ull, 0ull, 0ull, 0ull};
        {
            const char* hb = (const char*)h_s + cur * 8192 + kg * 16;
#pragma unroll
            for (int q = 0; q < 16; q++) {
#pragma unroll
                for (int b = 0; b < 4; b++) {
                    ulonglong2 u = *(const ulonglong2*)(hb + b * 2048 + q * 128);
                    acc[b] = ffma2(Wr[2 * q], u.x, acc[b]);
                    acc[b] = ffma2(Wr[2 * q + 1], u.y, acc[b]);
                }
            }
        }
        float s[4];
#pragma unroll
        for (int b = 0; b < 4; b++) {
            float2 f = unpack2(acc[b]);
            s[b] = f.x + f.y;
        }

        // ---- reduce over the 8 kg lanes (all lanes end with identical sums)
#pragma unroll
        for (int m = 1; m < 8; m <<= 1) {
#pragma unroll
            for (int b = 0; b < 4; b++)
                s[b] += __shfl_xor_sync(0xFFFFFFFF, s[b], m);
        }

        // ---- finalize: tanh on ALL lanes (identical), scatter outputs
        float hn[4];
#pragma unroll
        for (int b = 0; b < 4; b++) hn[b] = tanhf(s[b] + xr[b]);

        if (kg < 4)   // one writer lane per (j, b=kg)
            g_hs[((size_t)(bg * 4 + kg) * S_ + t) * H_ + jg] = hn[kg];

        if (t + 1 < S_) {
            // push to all 8 CTAs: 4 ST instructions, 32 lanes each
#pragma unroll
            for (int b = 0; b < 4; b++)
                st_cluster_f32(push_base + (unsigned)(nxt * 8192 + b * 2048), hn[b]);
#pragma unroll
            for (int b = 0; b < 4; b++) xr[b] = xn[b];
        } else {
            if (kg < 4)
                hfinal[(size_t)(bg * 4 + kg) * H_ + jg] = hn[kg];
        }

        __syncthreads();   // all lanes' pushes issued (and local STS drained)

        if (t + 1 < S_) {
            if (tid == 0) {
                asm volatile("fence.acq_rel.cluster;" ::: "memory");
#pragma unroll
                for (int r = 0; r < 8; r++)
                    mbar_arrive_cluster(peer_mb[r] + (unsigned)(nxt * 8));
            }
            if (nxt == 0) { mbar_wait_cluster(mb, p0);     p0 ^= 1; }
            else          { mbar_wait_cluster(mb + 8, p1); p1 ^= 1; }
        }
    }
}

// ---------------- launch ------------------------------------------------------
extern "C" void kernel_launch(void* const* d_in, const int* in_sizes, int n_in,
                              void* d_out, int out_size) {
    const float* inputs  = (const float*)d_in[0];
    const float* h0      = (const float*)d_in[1];
    const float* W_in_w  = (const float*)d_in[2];
    const float* W_in_b  = (const float*)d_in[3];
    const float* W_rec_w = (const float*)d_in[4];
    const float* W_out_w = (const float*)d_in[5];
    const float* W_out_b = (const float*)d_in[6];

    float* out    = (float*)d_out;                      // (B,S,O)
    float* hfinal = out + (size_t)B_ * S_ * O_;         // (B,H)

    // 1) xin = inputs @ W_in^T + b   -> g_xin
    {
        dim3 grid(B_ * S_ / 128, H_ / 128);
        gemm_kernel<H_, I_, false, true><<<grid, 256>>>(inputs, W_in_w, W_in_b, nullptr);
    }
    // 2) sequential scan: 16 clusters x 8 CTAs
    scan_kernel<<<128, 512>>>(h0, W_rec_w, hfinal);

    // 3) outputs = hs @ W_out^T + b  -> d_out
    {
        dim3 grid(B_ * S_ / 128, O_ / 128);
        gemm_kernel<O_, H_, true, false><<<grid, 256>>>(nullptr, W_out_w, W_out_b, out);
    }
}

// round 6
// speedup vs baseline: 2.8073x; 2.0316x over previous
#include <cuda_runtime.h>

#define B_ 64
#define S_ 2048
#define I_ 128
#define H_ 512
#define O_ 128

// ---------------- scratch (device globals: no allocations allowed) ----------
__device__ float g_xin[(size_t)B_ * S_ * H_];   // input projection (B,S,H)
__device__ float g_hs [(size_t)B_ * S_ * H_];   // hidden states   (B,S,H)
__device__ float g_h[2][B_ * H_];               // double-buffered h (plain [b][k])
__device__ unsigned g_bar[16];                  // per batch-group barrier

// ---------------- helpers ----------------------------------------------------
__device__ __forceinline__ unsigned long long ffma2(unsigned long long a,
                                                    unsigned long long b,
                                                    unsigned long long c) {
    unsigned long long d;
    asm("fma.rn.f32x2 %0, %1, %2, %3;" : "=l"(d) : "l"(a), "l"(b), "l"(c));
    return d;
}
__device__ __forceinline__ unsigned long long pack2(float x, float y) {
    unsigned long long p;
    asm("mov.b64 %0, {%1, %2};" : "=l"(p) : "f"(x), "f"(y));
    return p;
}
__device__ __forceinline__ float2 unpack2(unsigned long long p) {
    float2 r;
    asm("mov.b64 {%0, %1}, %2;" : "=f"(r.x), "=f"(r.y) : "l"(p));
    return r;
}

// ---------------- init: reset barriers ---------------------------------------
__global__ void init_kernel() {
    if (threadIdx.x < 16) g_bar[threadIdx.x] = 0;
}

// ---------------- tiled fp32 GEMM:  C[M,N] = A[M,K] @ B[N,K]^T + bias --------
template <int N, int K, bool SRC_HS, bool DST_XIN>
__global__ __launch_bounds__(256) void gemm_kernel(const float* __restrict__ Ap,
                                                   const float* __restrict__ Bm,
                                                   const float* __restrict__ bias,
                                                   float* __restrict__ Cp) {
    __shared__ __align__(16) float Ast[32][132];
    __shared__ __align__(16) float Bst[32][132];
    const float* A = SRC_HS ? g_hs : Ap;
    float* C = DST_XIN ? g_xin : Cp;

    const int tid = threadIdx.x;
    const int bm = blockIdx.x, bn = blockIdx.y;
    const float* Ab = A + (size_t)bm * 128 * K;
    const float* Bb = Bm + (size_t)bn * 128 * K;

    const int tx = tid & 15, ty = tid >> 4;
    unsigned long long acc2[4][8];
#pragma unroll
    for (int i = 0; i < 4; i++)
#pragma unroll
        for (int j = 0; j < 8; j++) acc2[i][j] = 0ull;

    for (int k0 = 0; k0 < K; k0 += 32) {
#pragma unroll
        for (int u = 0; u < 4; u++) {
            int idx4 = tid + u * 256;
            int m = idx4 >> 3;
            int kq = (idx4 & 7) * 4;
            float4 va = *(const float4*)&Ab[(size_t)m * K + k0 + kq];
            Ast[kq + 0][m] = va.x; Ast[kq + 1][m] = va.y;
            Ast[kq + 2][m] = va.z; Ast[kq + 3][m] = va.w;
            float4 vb = *(const float4*)&Bb[(size_t)m * K + k0 + kq];
            Bst[kq + 0][m] = vb.x; Bst[kq + 1][m] = vb.y;
            Bst[kq + 2][m] = vb.z; Bst[kq + 3][m] = vb.w;
        }
        __syncthreads();
#pragma unroll
        for (int kc = 0; kc < 32; kc++) {
            float4 a0 = *(const float4*)&Ast[kc][ty * 8];
            float4 a1 = *(const float4*)&Ast[kc][ty * 8 + 4];
            float4 b0 = *(const float4*)&Bst[kc][tx * 8];
            float4 b1 = *(const float4*)&Bst[kc][tx * 8 + 4];
            unsigned long long A2[4] = {pack2(a0.x, a0.y), pack2(a0.z, a0.w),
                                        pack2(a1.x, a1.y), pack2(a1.z, a1.w)};
            float bb[8] = {b0.x, b0.y, b0.z, b0.w, b1.x, b1.y, b1.z, b1.w};
#pragma unroll
            for (int j = 0; j < 8; j++) {
                unsigned long long B2 = pack2(bb[j], bb[j]);
#pragma unroll
                for (int i = 0; i < 4; i++) acc2[i][j] = ffma2(A2[i], B2, acc2[i][j]);
            }
        }
        __syncthreads();
    }
#pragma unroll
    for (int i = 0; i < 4; i++) {
        size_t m0 = (size_t)bm * 128 + ty * 8 + 2 * i;
#pragma unroll
        for (int j = 0; j < 8; j++) {
            int n = bn * 128 + tx * 8 + j;
            float2 v = unpack2(acc2[i][j]);
            C[m0 * N + n]       = v.x + bias[n];
            C[(m0 + 1) * N + n] = v.y + bias[n];
        }
    }
}

// ---------------- recurrent scan ---------------------------------------------
// 128 CTAs = 16 batch-groups (4 batches) x 8 output-slices (64 cols).
// Lane (jo=lane>>3, kg=lane&7): output j = ng*64 + w*4 + jo; K-slice kg*64.
// h in smem, permuted+swizzled float4 slots:
//   quad kq (=k/4) -> slot (kq&15)*8 + ((kq>>4) ^ (kq&7))
// so compute reads (warp: 8 kg lanes, jo-broadcast) are single 128B wavefronts
// AND the staging stores are conflict-free. Reduce over kg via shfl.bfly.
// Exchange via L2 double buffer + R1's proven atomic barrier.
__global__ __launch_bounds__(512, 1) void scan_kernel(const float* __restrict__ h0,
                                                      const float* __restrict__ Wrec,
                                                      float* __restrict__ hfinal) {
    __shared__ __align__(16) float h_s[4 * H_];     // 8 KB, permuted layout

    const int tid = threadIdx.x;
    const int bg = blockIdx.x >> 3;                 // batch-group 0..15
    const int ng = blockIdx.x & 7;                  // output slice 0..7
    const int w = tid >> 5, lane = tid & 31;
    const int kg = lane & 7;                        // K-slice 0..7 (64-wide)
    const int jo = lane >> 3;                       // 0..3
    const int jg = ng * 64 + w * 4 + jo;            // global output col

    // ---- W_rec[jg][kg*64 .. +63] as 32 k-pair-packed f32x2 regs
    unsigned long long Wr[32];
    {
        const float4* wp = (const float4*)&Wrec[(size_t)jg * H_ + kg * 64];
#pragma unroll
        for (int q = 0; q < 16; q++) {
            float4 v = wp[q];
            Wr[2 * q]     = pack2(v.x, v.y);
            Wr[2 * q + 1] = pack2(v.z, v.w);
        }
    }

    // ---- staging identity: b = tid>>7, quad kq = tid&127
    const int rb = tid >> 7;
    const int rkq = tid & 127;
    const int rslot = (rkq & 15) * 8 + (((rkq >> 4) ^ rkq) & 7);
    const size_t rsrc_off = (size_t)(bg * 4 + rb) * H_ + rkq * 4;

    // ---- per-(q) compute slot bases: slot(q,b,kg) = b*128 + q*8 + (kg^(q&7))
    const ulonglong2* h2 = (const ulonglong2*)h_s;

    // ---- preamble: h0 -> smem, xin t=0
    *(float4*)&h_s[rslot * 4] = *(const float4*)&h0[rsrc_off];
    // (rb folded into slot? no: slot array is [4][128] float4 slots)
    __syncthreads();
    // fix: staging wrote to slot without b offset — redo properly below
    __syncthreads();

    // NOTE: single clean staging implementation (b-offset included):
    // (the two syncthreads above are harmless; real store here)
    *(float4*)&h_s[(rb * 128 + rslot) * 4] = *(const float4*)&h0[rsrc_off];
    __syncthreads();

    float xr[4];
#pragma unroll
    for (int b = 0; b < 4; b++)
        xr[b] = g_xin[((size_t)(bg * 4 + b) * S_) * H_ + jg];

    for (int t = 0; t < S_; t++) {
        const int nxt = (t + 1) & 1;

        // ---- prefetch xin for t+1 (latency hidden under compute)
        float xn[4];
        if (t + 1 < S_) {
#pragma unroll
            for (int b = 0; b < 4; b++)
                xn[b] = g_xin[((size_t)(bg * 4 + b) * S_ + (t + 1)) * H_ + jg];
        }

        // ---- partial GEMM: 16 quads x 4 batches, k-pair packed f32x2
        unsigned long long acc[4] = {0ull, 0ull, 0ull, 0ull};
#pragma unroll
        for (int q = 0; q < 16; q++) {
            const int sl = q * 8 + (kg ^ (q & 7));
#pragma unroll
            for (int b = 0; b < 4; b++) {
                ulonglong2 u = h2[b * 128 + sl];
                acc[b] = ffma2(Wr[2 * q], u.x, acc[b]);
                acc[b] = ffma2(Wr[2 * q + 1], u.y, acc[b]);
            }
        }
        float s[4];
#pragma unroll
        for (int b = 0; b < 4; b++) {
            float2 f = unpack2(acc[b]);
            s[b] = f.x + f.y;
        }

        // ---- reduce over the 8 kg lanes (all lanes end identical)
#pragma unroll
        for (int m = 1; m < 8; m <<= 1) {
#pragma unroll
            for (int b = 0; b < 4; b++)
                s[b] += __shfl_xor_sync(0xFFFFFFFF, s[b], m);
        }

        // ---- tanh on all lanes; writer lanes (kg<4 -> b=kg) publish to L2
        float hn[4];
#pragma unroll
        for (int b = 0; b < 4; b++) hn[b] = tanhf(s[b] + xr[b]);

        if (kg < 4) {
            const int bglob = bg * 4 + kg;
            g_hs[((size_t)bglob * S_ + t) * H_ + jg] = hn[kg];
            if (t + 1 < S_) g_h[nxt][(size_t)bglob * H_ + jg] = hn[kg];
            else            hfinal[(size_t)bglob * H_ + jg] = hn[kg];
        }
#pragma unroll
        for (int b = 0; b < 4; b++) xr[b] = xn[b];

        if (t + 1 == S_) break;

        __syncthreads();   // all writers' STGs issued before elected fence

        // ---- per-batch-group barrier (8 CTAs) — R1's proven pattern
        if (tid == 0) {
            __threadfence();
            atomicAdd(&g_bar[bg], 1u);
            unsigned tgt = 8u * (unsigned)(t + 1);
            while (*(volatile unsigned*)&g_bar[bg] < tgt) { }
            __threadfence();
        }
        __syncthreads();

        // ---- reload full h(t+1) from L2 into permuted smem
        *(float4*)&h_s[(rb * 128 + rslot) * 4] =
            *(const float4*)&g_h[nxt][rsrc_off];
        __syncthreads();
    }
}

// ---------------- launch ------------------------------------------------------
extern "C" void kernel_launch(void* const* d_in, const int* in_sizes, int n_in,
                              void* d_out, int out_size) {
    const float* inputs  = (const float*)d_in[0];
    const float* h0      = (const float*)d_in[1];
    const float* W_in_w  = (const float*)d_in[2];
    const float* W_in_b  = (const float*)d_in[3];
    const float* W_rec_w = (const float*)d_in[4];
    const float* W_out_w = (const float*)d_in[5];
    const float* W_out_b = (const float*)d_in[6];

    float* out    = (float*)d_out;                      // (B,S,O)
    float* hfinal = out + (size_t)B_ * S_ * O_;         // (B,H)

    // 1) xin = inputs @ W_in^T + b   -> g_xin
    {
        dim3 grid(B_ * S_ / 128, H_ / 128);
        gemm_kernel<H_, I_, false, true><<<grid, 256>>>(inputs, W_in_w, W_in_b, nullptr);
    }
    // 2) barrier reset
    init_kernel<<<1, 32>>>();

    // 3) sequential scan: 128 co-resident CTAs, L2 exchange
    scan_kernel<<<128, 512>>>(h0, W_rec_w, hfinal);

    // 4) outputs = hs @ W_out^T + b  -> d_out
    {
        dim3 grid(B_ * S_ / 128, O_ / 128);
        gemm_kernel<O_, H_, true, false><<<grid, 256>>>(nullptr, W_out_w, W_out_b, out);
    }
}